// round 6
// baseline (speedup 1.0000x reference)
#include <cuda_runtime.h>
#include <cuda_bf16.h>
#include <cstdint>

#define D65 65
#define K0  4225
#define KP  4352
#define K3  13056           // 3*KP
#define MROWS 8192
#define LSEQ 1024
#define BK  64
#define NT  (K3 / BK)       // 204 k-tiles of 64

// ---------------- scratch ----------------
__device__ __nv_bfloat16 g_Ah[(size_t)MROWS * K3];  // [m][Xh|Xh|Xl]
__device__ __nv_bfloat16 g_Rp[(size_t)MROWS * K3];  // [m][Rh|Rl|Rh]
__device__ __nv_bfloat16 g_Bw[(size_t)KP    * K3];  // [(b,d)][Wh|Wl|Wh] (pads stay 0)
__device__ __nv_bfloat16 g_Qp[(size_t)MROWS * K3];  // [m][Qh|Qh|Ql]

// smem: 3 stages x (A 128x64 + B 128x64 bf16), 128B rows, XOR swizzle
#define TILE_B    (128 * 128)            // 16384 B per tile
#define STAGE_B   (2 * TILE_B)           // 32768 B
#define SMEM_SZ   (3 * STAGE_B)          // 98304 B

// ---------------- PTX helpers ----------------
__device__ __forceinline__ uint32_t s2u(const void* p) {
    uint32_t a;
    asm("{ .reg .u64 t; cvta.to.shared.u64 t, %1; cvt.u32.u64 %0, t; }"
        : "=r"(a) : "l"(p));
    return a;
}
__device__ __forceinline__ void cp16(uint32_t s, const void* g) {
    asm volatile("cp.async.cg.shared.global [%0], [%1], 16;\n" :: "r"(s), "l"(g));
}
#define CP_COMMIT() asm volatile("cp.async.commit_group;\n" ::: "memory")
#define CP_WAIT1()  asm volatile("cp.async.wait_group 1;\n" ::: "memory")

#define LDM_X4(r0, r1, r2, r3, a)                                              \
    asm volatile("ldmatrix.sync.aligned.m8n8.x4.shared.b16 {%0,%1,%2,%3}, [%4];" \
        : "=r"(r0), "=r"(r1), "=r"(r2), "=r"(r3) : "r"(a))

#define MMA16816(c, a, b0, b1)                                                 \
    asm volatile("mma.sync.aligned.m16n8k16.row.col.f32.bf16.bf16.f32 "        \
        "{%0,%1,%2,%3}, {%4,%5,%6,%7}, {%8,%9}, {%0,%1,%2,%3};"                \
        : "+f"((c)[0]), "+f"((c)[1]), "+f"((c)[2]), "+f"((c)[3])               \
        : "r"((a)[0]), "r"((a)[1]), "r"((a)[2]), "r"((a)[3]),                  \
          "r"(b0), "r"(b1))

// ---------------- prep kernels ----------------
__global__ void prep_XR(const float* __restrict__ l1, const float* __restrict__ l2,
                        const float* __restrict__ h1, const float* __restrict__ h2) {
    int m = blockIdx.y;
    int k = blockIdx.x * blockDim.x + threadIdx.x;   // 0..KP-1
    float xv = 0.f, rv = 0.f;
    if (k < K0) {
        int a = k / D65, c = k - a * D65;
        float l1v = (a < 64) ? l1[m * 64 + a] : 1.0f;
        float l2v = (a < 64) ? l2[m * 64 + a] : 1.0f;
        xv = l1v * h1[m * D65 + c];
        rv = l2v * h2[m * D65 + c];
    }
    __nv_bfloat16 xh = __float2bfloat16(xv);
    __nv_bfloat16 xl = __float2bfloat16(xv - __bfloat162float(xh));
    __nv_bfloat16 rh = __float2bfloat16(rv);
    __nv_bfloat16 rl = __float2bfloat16(rv - __bfloat162float(rh));
    size_t base = (size_t)m * K3;
    g_Ah[base + k]          = xh;
    g_Ah[base + KP + k]     = xh;
    g_Ah[base + 2 * KP + k] = xl;
    g_Rp[base + k]          = rh;
    g_Rp[base + KP + k]     = rl;
    g_Rp[base + 2 * KP + k] = rh;
}

// g_Bw[(b*65+d)][a*65+c] = W[a][b][c][d], hi/lo split -> [Wh|Wl|Wh]
__global__ void prep_W(const float* __restrict__ W) {
    __shared__ float s[K0];
    int ab = blockIdx.x;
    int a = ab / D65, b = ab - a * D65;
    const float* Wab = W + (size_t)ab * K0;
    for (int i = threadIdx.x; i < K0; i += blockDim.x) s[i] = Wab[i];
    __syncthreads();
    for (int i = threadIdx.x; i < K0; i += blockDim.x) {
        int d = i / D65, c = i - d * D65;
        float v = s[c * D65 + d];
        __nv_bfloat16 h = __float2bfloat16(v);
        __nv_bfloat16 l = __float2bfloat16(v - __bfloat162float(h));
        size_t row = (size_t)(b * D65 + d) * K3;
        int kk = a * D65 + c;
        g_Bw[row + kk]          = h;
        g_Bw[row + KP + kk]     = l;
        g_Bw[row + 2 * KP + kk] = h;
    }
}

// ---------------- stage loader: 128x64 bf16 for A and B -------------------
// smem addr: row*128 + ((chunk ^ (row&7)) * 16), chunk = 16B column index
__device__ __forceinline__ void load_stage(uint32_t smA, uint32_t smB,
                                           const __nv_bfloat16* Ab,
                                           const __nv_bfloat16* Bb, int tid) {
#pragma unroll
    for (int t = 0; t < 4; t++) {
        int id = tid + t * 256;
        int r = id >> 3, c = id & 7;
        uint32_t off = r * 128 + ((c ^ (r & 7)) << 4);
        cp16(smA + off, Ab + (size_t)r * K3 + c * 8);
        cp16(smB + off, Bb + (size_t)r * K3 + c * 8);
    }
}

// ---------------- fragment loaders ---------------------------------------
__device__ __forceinline__ void ld_af(uint32_t af[2][4], uint32_t sA,
                                      int a_row, int a_ch, int kc) {
#pragma unroll
    for (int i = 0; i < 2; i++) {
        int r = a_row + 16 * i;
        uint32_t addr = sA + r * 128 + (((kc + a_ch) ^ (r & 7)) << 4);
        LDM_X4(af[i][0], af[i][1], af[i][2], af[i][3], addr);
    }
}
__device__ __forceinline__ void ld_bf(uint32_t bf[8][2], uint32_t sB,
                                      int b_row, int b_ch, int kc) {
#pragma unroll
    for (int j2 = 0; j2 < 4; j2++) {
        int r = b_row + 16 * j2;
        uint32_t addr = sB + r * 128 + (((kc + b_ch) ^ (r & 7)) << 4);
        LDM_X4(bf[2 * j2][0], bf[2 * j2][1],
               bf[2 * j2 + 1][0], bf[2 * j2 + 1][1], addr);
    }
}

// ---------------- HMMA mainloop: acc[2][8][4] = A(128xK3) * B(128xK3)^T ---
__device__ __forceinline__ void hmma_loop(const __nv_bfloat16* Abase,
                                          const __nv_bfloat16* Bbase,
                                          uint32_t smb, int tid,
                                          float acc[2][8][4]) {
    int lane = tid & 31, wid = tid >> 5;
    int warp_m = wid & 3, warp_n = wid >> 2;

#pragma unroll
    for (int i = 0; i < 2; i++)
#pragma unroll
        for (int j = 0; j < 8; j++)
#pragma unroll
            for (int t = 0; t < 4; t++) acc[i][j][t] = 0.f;

    // ldmatrix per-lane rows and 8-element column halves
    int a_row  = 32 * warp_m + (lane & 7) + ((lane >> 3) & 1) * 8;
    int a_ch   = (lane >> 4) & 1;          // 8-elem half -> chunk offset
    int b_row  = 64 * warp_n + (lane & 7) + ((lane >> 4) & 1) * 8;
    int b_ch   = (lane >> 3) & 1;

    load_stage(smb, smb + TILE_B, Abase, Bbase, tid);
    CP_COMMIT();
    load_stage(smb + STAGE_B, smb + STAGE_B + TILE_B, Abase + BK, Bbase + BK, tid);
    CP_COMMIT();

    for (int kt = 0; kt < NT; kt++) {
        CP_WAIT1();
        __syncthreads();
        uint32_t sA = smb + (kt % 3) * STAGE_B;
        uint32_t sB = sA + TILE_B;
        if (kt + 2 < NT) {
            uint32_t sN = smb + ((kt + 2) % 3) * STAGE_B;
            load_stage(sN, sN + TILE_B,
                       Abase + (size_t)(kt + 2) * BK,
                       Bbase + (size_t)(kt + 2) * BK, tid);
        }
        CP_COMMIT();

        // double-buffered fragments: LDSM for ks+1 hides under mma of ks
        uint32_t af[2][2][4];
        uint32_t bf[2][8][2];
        ld_af(af[0], sA, a_row, a_ch, 0);
        ld_bf(bf[0], sB, b_row, b_ch, 0);
#pragma unroll
        for (int ks = 0; ks < 4; ks++) {
            int cur = ks & 1, nxt = cur ^ 1;
            if (ks < 3) {
                ld_af(af[nxt], sA, a_row, a_ch, (ks + 1) * 2);
                ld_bf(bf[nxt], sB, b_row, b_ch, (ks + 1) * 2);
            }
#pragma unroll
            for (int i = 0; i < 2; i++)
#pragma unroll
                for (int j = 0; j < 8; j++)
                    MMA16816(acc[i][j], af[cur][i], bf[cur][j][0], bf[cur][j][1]);
        }
        // no trailing barrier: next iteration's top barrier protects reuse
    }
}

// ---------------- GEMM1: Q' = A' @ Bw'^T, epilogue hi/hi/lo bf16 ---------
__global__ void __launch_bounds__(256, 2) gemm1_kernel() {
    extern __shared__ char sm[];
    uint32_t smb = s2u(sm);
    int tid = threadIdx.x, lane = tid & 31, wid = tid >> 5;
    int warp_m = wid & 3, warp_n = wid >> 2;
    int brow = blockIdx.y * 128, bn = blockIdx.x * 128;

    float acc[2][8][4];
    hmma_loop(g_Ah + (size_t)brow * K3, g_Bw + (size_t)bn * K3, smb, tid, acc);

    int row0 = brow + 32 * warp_m + (lane >> 2);
    int col0 = bn + 64 * warp_n + (lane & 3) * 2;
#pragma unroll
    for (int i = 0; i < 2; i++) {
#pragma unroll
        for (int j = 0; j < 8; j++) {
#pragma unroll
            for (int half = 0; half < 2; half++) {
                int r = row0 + 16 * i + 8 * half;
                int c = col0 + 8 * j;
                float v0 = acc[i][j][2 * half];
                float v1 = acc[i][j][2 * half + 1];
                __nv_bfloat162 hh, ll;
                hh.x = __float2bfloat16(v0);
                hh.y = __float2bfloat16(v1);
                ll.x = __float2bfloat16(v0 - __bfloat162float(hh.x));
                ll.y = __float2bfloat16(v1 - __bfloat162float(hh.y));
                size_t rb = (size_t)r * K3;
                *reinterpret_cast<__nv_bfloat162*>(&g_Qp[rb + c]) = hh;
                *reinterpret_cast<__nv_bfloat162*>(&g_Qp[rb + KP + c]) = hh;
                *reinterpret_cast<__nv_bfloat162*>(&g_Qp[rb + 2 * KP + c]) = ll;
            }
        }
    }
}

// ---------------- GEMM2: out[n] = Q'[n] @ R'[n]^T, fp32 epilogue ----------
__global__ void __launch_bounds__(256, 2) gemm2_kernel(float* __restrict__ out) {
    extern __shared__ char sm[];
    uint32_t smb = s2u(sm);
    int tid = threadIdx.x, lane = tid & 31, wid = tid >> 5;
    int warp_m = wid & 3, warp_n = wid >> 2;
    int nb = blockIdx.z;
    int brow = blockIdx.y * 128, bn = blockIdx.x * 128;

    float acc[2][8][4];
    hmma_loop(g_Qp + ((size_t)nb * LSEQ + brow) * K3,
              g_Rp + ((size_t)nb * LSEQ + bn) * K3, smb, tid, acc);

    int row0 = brow + 32 * warp_m + (lane >> 2);
    int col0 = bn + 64 * warp_n + (lane & 3) * 2;
    float* obase = out + (size_t)nb * LSEQ * LSEQ;
#pragma unroll
    for (int i = 0; i < 2; i++) {
#pragma unroll
        for (int j = 0; j < 8; j++) {
#pragma unroll
            for (int half = 0; half < 2; half++) {
                int r = row0 + 16 * i + 8 * half;
                int c = col0 + 8 * j;
                float2 v = make_float2(acc[i][j][2 * half], acc[i][j][2 * half + 1]);
                *reinterpret_cast<float2*>(&obase[(size_t)r * LSEQ + c]) = v;
            }
        }
    }
}

// ---------------- launcher ------------------------------------------------
extern "C" void kernel_launch(void* const* d_in, const int* in_sizes, int n_in,
                              void* d_out, int out_size) {
    const float* l1 = (const float*)d_in[0];
    const float* l2 = (const float*)d_in[1];
    const float* h1 = (const float*)d_in[3];
    const float* h2 = (const float*)d_in[4];
    const float* W  = (const float*)d_in[6];
    float* out = (float*)d_out;

    cudaFuncSetAttribute(gemm1_kernel, cudaFuncAttributeMaxDynamicSharedMemorySize, SMEM_SZ);
    cudaFuncSetAttribute(gemm2_kernel, cudaFuncAttributeMaxDynamicSharedMemorySize, SMEM_SZ);

    prep_XR<<<dim3(17, MROWS), 256>>>(l1, l2, h1, h2);
    prep_W<<<D65 * D65, 256>>>(W);
    gemm1_kernel<<<dim3(34, 64), 256, SMEM_SZ>>>();
    gemm2_kernel<<<dim3(8, 8, 8), 256, SMEM_SZ>>>(out);
}

// round 9
// speedup vs baseline: 1.4873x; 1.4873x over previous
#include <cuda_runtime.h>
#include <cuda_fp16.h>
#include <cstdint>

#define D65 65
#define K0  4225
#define KP  4352
#define K2  8704            // 2*KP
#define MROWS 8192
#define LSEQ 1024
#define BK  64
#define NT  (K2 / BK)       // 136 k-tiles of 64

// ---------------- scratch ----------------
__device__ __half g_Ah[(size_t)MROWS * K2];  // [m][Xh|Xl]
__device__ __half g_Rp[(size_t)MROWS * K2];  // [m][Rh|Rh]
__device__ __half g_Bw[(size_t)KP    * K2];  // [(b,d)][Wh|Wh] (pads stay 0)
__device__ __half g_Qp[(size_t)MROWS * K2];  // [m][Qh|Ql]

// smem: 3 stages x (A 128x64 + B 128x64 fp16), 128B rows, XOR swizzle
#define TILE_B    (128 * 128)            // 16384 B per tile
#define STAGE_B   (2 * TILE_B)           // 32768 B
#define SMEM_SZ   (3 * STAGE_B)          // 98304 B

// ---------------- PTX helpers ----------------
__device__ __forceinline__ uint32_t s2u(const void* p) {
    uint32_t a;
    asm("{ .reg .u64 t; cvta.to.shared.u64 t, %1; cvt.u32.u64 %0, t; }"
        : "=r"(a) : "l"(p));
    return a;
}
__device__ __forceinline__ void cp16(uint32_t s, const void* g) {
    asm volatile("cp.async.cg.shared.global [%0], [%1], 16;\n" :: "r"(s), "l"(g));
}
#define CP_COMMIT() asm volatile("cp.async.commit_group;\n" ::: "memory")
#define CP_WAIT1()  asm volatile("cp.async.wait_group 1;\n" ::: "memory")

#define LDM_X4(r0, r1, r2, r3, a)                                              \
    asm volatile("ldmatrix.sync.aligned.m8n8.x4.shared.b16 {%0,%1,%2,%3}, [%4];" \
        : "=r"(r0), "=r"(r1), "=r"(r2), "=r"(r3) : "r"(a))

#define MMA16816(c, a, b0, b1)                                                 \
    asm volatile("mma.sync.aligned.m16n8k16.row.col.f32.f16.f16.f32 "          \
        "{%0,%1,%2,%3}, {%4,%5,%6,%7}, {%8,%9}, {%0,%1,%2,%3};"                \
        : "+f"((c)[0]), "+f"((c)[1]), "+f"((c)[2]), "+f"((c)[3])               \
        : "r"((a)[0]), "r"((a)[1]), "r"((a)[2]), "r"((a)[3]),                  \
          "r"(b0), "r"(b1))

// ---------------- prep kernels ----------------
__global__ void prep_XR(const float* __restrict__ l1, const float* __restrict__ l2,
                        const float* __restrict__ h1, const float* __restrict__ h2) {
    int m = blockIdx.y;
    int k = blockIdx.x * blockDim.x + threadIdx.x;   // 0..KP-1
    float xv = 0.f, rv = 0.f;
    if (k < K0) {
        int a = k / D65, c = k - a * D65;
        float l1v = (a < 64) ? l1[m * 64 + a] : 1.0f;
        float l2v = (a < 64) ? l2[m * 64 + a] : 1.0f;
        xv = l1v * h1[m * D65 + c];
        rv = l2v * h2[m * D65 + c];
    }
    __half xh = __float2half_rn(xv);
    __half xl = __float2half_rn(xv - __half2float(xh));
    __half rh = __float2half_rn(rv);
    size_t base = (size_t)m * K2;
    g_Ah[base + k]      = xh;
    g_Ah[base + KP + k] = xl;
    g_Rp[base + k]      = rh;
    g_Rp[base + KP + k] = rh;
}

// g_Bw[(b*65+d)][a*65+c] = W[a][b][c][d] rounded to fp16, layout [Wh|Wh]
__global__ void prep_W(const float* __restrict__ W) {
    __shared__ float s[K0];
    int ab = blockIdx.x;
    int a = ab / D65, b = ab - a * D65;
    const float* Wab = W + (size_t)ab * K0;
    for (int i = threadIdx.x; i < K0; i += blockDim.x) s[i] = Wab[i];
    __syncthreads();
    for (int i = threadIdx.x; i < K0; i += blockDim.x) {
        int d = i / D65, c = i - d * D65;
        __half h = __float2half_rn(s[c * D65 + d]);
        size_t row = (size_t)(b * D65 + d) * K2;
        int kk = a * D65 + c;
        g_Bw[row + kk]      = h;
        g_Bw[row + KP + kk] = h;
    }
}

// ---------------- stage loader: 128x64 fp16 for A and B -------------------
// smem addr: row*128 + ((chunk ^ (row&7)) * 16), chunk = 16B column index
__device__ __forceinline__ void load_stage(uint32_t smA, uint32_t smB,
                                           const __half* Ab,
                                           const __half* Bb, int tid) {
#pragma unroll
    for (int t = 0; t < 4; t++) {
        int id = tid + t * 256;
        int r = id >> 3, c = id & 7;
        uint32_t off = r * 128 + ((c ^ (r & 7)) << 4);
        cp16(smA + off, Ab + (size_t)r * K2 + c * 8);
        cp16(smB + off, Bb + (size_t)r * K2 + c * 8);
    }
}

// ---------------- HMMA mainloop: acc[2][8][4] = A(128xK2) * B(128xK2)^T ---
__device__ __forceinline__ void hmma_loop(const __half* Abase,
                                          const __half* Bbase,
                                          uint32_t smb, int tid,
                                          float acc[2][8][4]) {
    int lane = tid & 31, wid = tid >> 5;
    int warp_m = wid & 3, warp_n = wid >> 2;

#pragma unroll
    for (int i = 0; i < 2; i++)
#pragma unroll
        for (int j = 0; j < 8; j++)
#pragma unroll
            for (int t = 0; t < 4; t++) acc[i][j][t] = 0.f;

    // ldmatrix per-lane rows and 8-element column halves
    int a_row  = 32 * warp_m + (lane & 7) + ((lane >> 3) & 1) * 8;
    int a_ch   = (lane >> 4) & 1;          // 8-elem half -> chunk offset
    int b_row  = 64 * warp_n + (lane & 7) + ((lane >> 4) & 1) * 8;
    int b_ch   = (lane >> 3) & 1;

    load_stage(smb, smb + TILE_B, Abase, Bbase, tid);
    CP_COMMIT();
    load_stage(smb + STAGE_B, smb + STAGE_B + TILE_B, Abase + BK, Bbase + BK, tid);
    CP_COMMIT();

    for (int kt = 0; kt < NT; kt++) {
        CP_WAIT1();
        __syncthreads();
        uint32_t sA = smb + (kt % 3) * STAGE_B;
        uint32_t sB = sA + TILE_B;
        if (kt + 2 < NT) {
            uint32_t sN = smb + ((kt + 2) % 3) * STAGE_B;
            load_stage(sN, sN + TILE_B,
                       Abase + (size_t)(kt + 2) * BK,
                       Bbase + (size_t)(kt + 2) * BK, tid);
        }
        CP_COMMIT();

#pragma unroll
        for (int ks = 0; ks < 4; ks++) {
            int kc = ks * 2;                 // base 16B-chunk of this k16
            uint32_t af[2][4];
#pragma unroll
            for (int i = 0; i < 2; i++) {
                int r = a_row + 16 * i;
                uint32_t addr = sA + r * 128 + (((kc + a_ch) ^ (r & 7)) << 4);
                LDM_X4(af[i][0], af[i][1], af[i][2], af[i][3], addr);
            }
            uint32_t bf[8][2];
#pragma unroll
            for (int j2 = 0; j2 < 4; j2++) {
                int r = b_row + 16 * j2;
                uint32_t addr = sB + r * 128 + (((kc + b_ch) ^ (r & 7)) << 4);
                LDM_X4(bf[2 * j2][0], bf[2 * j2][1],
                       bf[2 * j2 + 1][0], bf[2 * j2 + 1][1], addr);
            }
#pragma unroll
            for (int i = 0; i < 2; i++)
#pragma unroll
                for (int j = 0; j < 8; j++)
                    MMA16816(acc[i][j], af[i], bf[j][0], bf[j][1]);
        }
        // no trailing barrier: next iteration's top barrier protects reuse
    }
}

// ---------------- GEMM1: Q = X' @ W'^T, epilogue hi/lo fp16 ---------------
__global__ void __launch_bounds__(256, 2) gemm1_kernel() {
    extern __shared__ char sm[];
    uint32_t smb = s2u(sm);
    int tid = threadIdx.x, lane = tid & 31, wid = tid >> 5;
    int warp_m = wid & 3, warp_n = wid >> 2;
    int brow = blockIdx.y * 128, bn = blockIdx.x * 128;

    float acc[2][8][4];
    hmma_loop(g_Ah + (size_t)brow * K2, g_Bw + (size_t)bn * K2, smb, tid, acc);

    int row0 = brow + 32 * warp_m + (lane >> 2);
    int col0 = bn + 64 * warp_n + (lane & 3) * 2;
#pragma unroll
    for (int i = 0; i < 2; i++) {
#pragma unroll
        for (int j = 0; j < 8; j++) {
#pragma unroll
            for (int half = 0; half < 2; half++) {
                int r = row0 + 16 * i + 8 * half;
                int c = col0 + 8 * j;
                float v0 = acc[i][j][2 * half];
                float v1 = acc[i][j][2 * half + 1];
                __half2 hh, ll;
                hh.x = __float2half_rn(v0);
                hh.y = __float2half_rn(v1);
                ll.x = __float2half_rn(v0 - __half2float(hh.x));
                ll.y = __float2half_rn(v1 - __half2float(hh.y));
                size_t rb = (size_t)r * K2;
                *reinterpret_cast<__half2*>(&g_Qp[rb + c]) = hh;
                *reinterpret_cast<__half2*>(&g_Qp[rb + KP + c]) = ll;
            }
        }
    }
}

// ---------------- GEMM2: out[n] = Q'[n] @ R'[n]^T, fp32 epilogue ----------
__global__ void __launch_bounds__(256, 2) gemm2_kernel(float* __restrict__ out) {
    extern __shared__ char sm[];
    uint32_t smb = s2u(sm);
    int tid = threadIdx.x, lane = tid & 31, wid = tid >> 5;
    int warp_m = wid & 3, warp_n = wid >> 2;
    int nb = blockIdx.z;
    int brow = blockIdx.y * 128, bn = blockIdx.x * 128;

    float acc[2][8][4];
    hmma_loop(g_Qp + ((size_t)nb * LSEQ + brow) * K2,
              g_Rp + ((size_t)nb * LSEQ + bn) * K2, smb, tid, acc);

    int row0 = brow + 32 * warp_m + (lane >> 2);
    int col0 = bn + 64 * warp_n + (lane & 3) * 2;
    float* obase = out + (size_t)nb * LSEQ * LSEQ;
#pragma unroll
    for (int i = 0; i < 2; i++) {
#pragma unroll
        for (int j = 0; j < 8; j++) {
#pragma unroll
            for (int half = 0; half < 2; half++) {
                int r = row0 + 16 * i + 8 * half;
                int c = col0 + 8 * j;
                float2 v = make_float2(acc[i][j][2 * half], acc[i][j][2 * half + 1]);
                *reinterpret_cast<float2*>(&obase[(size_t)r * LSEQ + c]) = v;
            }
        }
    }
}

// ---------------- launcher ------------------------------------------------
extern "C" void kernel_launch(void* const* d_in, const int* in_sizes, int n_in,
                              void* d_out, int out_size) {
    const float* l1 = (const float*)d_in[0];
    const float* l2 = (const float*)d_in[1];
    const float* h1 = (const float*)d_in[3];
    const float* h2 = (const float*)d_in[4];
    const float* W  = (const float*)d_in[6];
    float* out = (float*)d_out;

    cudaFuncSetAttribute(gemm1_kernel, cudaFuncAttributeMaxDynamicSharedMemorySize, SMEM_SZ);
    cudaFuncSetAttribute(gemm2_kernel, cudaFuncAttributeMaxDynamicSharedMemorySize, SMEM_SZ);

    prep_XR<<<dim3(17, MROWS), 256>>>(l1, l2, h1, h2);
    prep_W<<<D65 * D65, 256>>>(W);
    gemm1_kernel<<<dim3(34, 64), 256, SMEM_SZ>>>();
    gemm2_kernel<<<dim3(8, 8, 8), 256, SMEM_SZ>>>(out);
}

// round 11
// speedup vs baseline: 2.7977x; 1.8810x over previous
#include <cuda_runtime.h>
#include <cuda_fp16.h>
#include <cstdint>

#define D65 65
#define K0  4225
#define KP  4352            // padded K (single-term fp16)
#define MROWS 8192
#define LSEQ 1024
#define BK  64
#define NT  (KP / BK)       // 68 k-tiles of 64

// ---------------- scratch ----------------
__device__ __half g_A[(size_t)MROWS * KP];  // [m][Xh]
__device__ __half g_R[(size_t)MROWS * KP];  // [m][Rh]
__device__ __half g_B[(size_t)KP    * KP];  // [(b,d)][Wh] (pads stay 0)
__device__ __half g_Q[(size_t)MROWS * KP];  // [m][Qh]

// smem: 3 stages x (A 128x64 + B 128x64 fp16), 128B rows, XOR swizzle
#define TILE_B    (128 * 128)            // 16384 B per tile
#define STAGE_B   (2 * TILE_B)           // 32768 B
#define SMEM_SZ   (3 * STAGE_B)          // 98304 B

// ---------------- PTX helpers ----------------
__device__ __forceinline__ uint32_t s2u(const void* p) {
    uint32_t a;
    asm("{ .reg .u64 t; cvta.to.shared.u64 t, %1; cvt.u32.u64 %0, t; }"
        : "=r"(a) : "l"(p));
    return a;
}
__device__ __forceinline__ void cp16(uint32_t s, const void* g) {
    asm volatile("cp.async.cg.shared.global [%0], [%1], 16;\n" :: "r"(s), "l"(g));
}
#define CP_COMMIT() asm volatile("cp.async.commit_group;\n" ::: "memory")
#define CP_WAIT1()  asm volatile("cp.async.wait_group 1;\n" ::: "memory")

#define LDM_X4(r0, r1, r2, r3, a)                                              \
    asm volatile("ldmatrix.sync.aligned.m8n8.x4.shared.b16 {%0,%1,%2,%3}, [%4];" \
        : "=r"(r0), "=r"(r1), "=r"(r2), "=r"(r3) : "r"(a))

#define MMA16816(c, a, b0, b1)                                                 \
    asm volatile("mma.sync.aligned.m16n8k16.row.col.f32.f16.f16.f32 "          \
        "{%0,%1,%2,%3}, {%4,%5,%6,%7}, {%8,%9}, {%0,%1,%2,%3};"                \
        : "+f"((c)[0]), "+f"((c)[1]), "+f"((c)[2]), "+f"((c)[3])               \
        : "r"((a)[0]), "r"((a)[1]), "r"((a)[2]), "r"((a)[3]),                  \
          "r"(b0), "r"(b1))

// ---------------- prep kernels ----------------
__global__ void prep_XR(const float* __restrict__ l1, const float* __restrict__ l2,
                        const float* __restrict__ h1, const float* __restrict__ h2) {
    int m = blockIdx.y;
    int k = blockIdx.x * blockDim.x + threadIdx.x;   // 0..KP-1
    float xv = 0.f, rv = 0.f;
    if (k < K0) {
        int a = k / D65, c = k - a * D65;
        float l1v = (a < 64) ? l1[m * 64 + a] : 1.0f;
        float l2v = (a < 64) ? l2[m * 64 + a] : 1.0f;
        xv = l1v * h1[m * D65 + c];
        rv = l2v * h2[m * D65 + c];
    }
    size_t base = (size_t)m * KP;
    g_A[base + k] = __float2half_rn(xv);
    g_R[base + k] = __float2half_rn(rv);
}

// g_B[(b*65+d)][a*65+c] = W[a][b][c][d] rounded to fp16
__global__ void prep_W(const float* __restrict__ W) {
    __shared__ float s[K0];
    int ab = blockIdx.x;
    int a = ab / D65, b = ab - a * D65;
    const float* Wab = W + (size_t)ab * K0;
    for (int i = threadIdx.x; i < K0; i += blockDim.x) s[i] = Wab[i];
    __syncthreads();
    for (int i = threadIdx.x; i < K0; i += blockDim.x) {
        int d = i / D65, c = i - d * D65;
        g_B[(size_t)(b * D65 + d) * KP + a * D65 + c] = __float2half_rn(s[c * D65 + d]);
    }
}

// ---------------- stage loader: 128x64 fp16 for A and B -------------------
// smem addr: row*128 + ((chunk ^ (row&7)) * 16), chunk = 16B column index
__device__ __forceinline__ void load_stage(uint32_t smA, uint32_t smB,
                                           const __half* Ab,
                                           const __half* Bb, int tid) {
#pragma unroll
    for (int t = 0; t < 4; t++) {
        int id = tid + t * 256;
        int r = id >> 3, c = id & 7;
        uint32_t off = r * 128 + ((c ^ (r & 7)) << 4);
        cp16(smA + off, Ab + (size_t)r * KP + c * 8);
        cp16(smB + off, Bb + (size_t)r * KP + c * 8);
    }
}

// ---------------- HMMA mainloop: acc[2][8][4] = A(128xKP) * B(128xKP)^T ---
__device__ __forceinline__ void hmma_loop(const __half* Abase,
                                          const __half* Bbase,
                                          uint32_t smb, int tid,
                                          float acc[2][8][4]) {
    int lane = tid & 31, wid = tid >> 5;
    int warp_m = wid & 3, warp_n = wid >> 2;

#pragma unroll
    for (int i = 0; i < 2; i++)
#pragma unroll
        for (int j = 0; j < 8; j++)
#pragma unroll
            for (int t = 0; t < 4; t++) acc[i][j][t] = 0.f;

    // ldmatrix per-lane rows and 8-element column halves
    int a_row  = 32 * warp_m + (lane & 7) + ((lane >> 3) & 1) * 8;
    int a_ch   = (lane >> 4) & 1;          // 8-elem half -> chunk offset
    int b_row  = 64 * warp_n + (lane & 7) + ((lane >> 4) & 1) * 8;
    int b_ch   = (lane >> 3) & 1;

    load_stage(smb, smb + TILE_B, Abase, Bbase, tid);
    CP_COMMIT();
    load_stage(smb + STAGE_B, smb + STAGE_B + TILE_B, Abase + BK, Bbase + BK, tid);
    CP_COMMIT();

    for (int kt = 0; kt < NT; kt++) {
        CP_WAIT1();
        __syncthreads();
        uint32_t sA = smb + (kt % 3) * STAGE_B;
        uint32_t sB = sA + TILE_B;
        if (kt + 2 < NT) {
            uint32_t sN = smb + ((kt + 2) % 3) * STAGE_B;
            load_stage(sN, sN + TILE_B,
                       Abase + (size_t)(kt + 2) * BK,
                       Bbase + (size_t)(kt + 2) * BK, tid);
        }
        CP_COMMIT();

#pragma unroll
        for (int ks = 0; ks < 4; ks++) {
            int kc = ks * 2;                 // base 16B-chunk of this k16
            uint32_t af[2][4];
#pragma unroll
            for (int i = 0; i < 2; i++) {
                int r = a_row + 16 * i;
                uint32_t addr = sA + r * 128 + (((kc + a_ch) ^ (r & 7)) << 4);
                LDM_X4(af[i][0], af[i][1], af[i][2], af[i][3], addr);
            }
            uint32_t bf[8][2];
#pragma unroll
            for (int j2 = 0; j2 < 4; j2++) {
                int r = b_row + 16 * j2;
                uint32_t addr = sB + r * 128 + (((kc + b_ch) ^ (r & 7)) << 4);
                LDM_X4(bf[2 * j2][0], bf[2 * j2][1],
                       bf[2 * j2 + 1][0], bf[2 * j2 + 1][1], addr);
            }
#pragma unroll
            for (int i = 0; i < 2; i++)
#pragma unroll
                for (int j = 0; j < 8; j++)
                    MMA16816(acc[i][j], af[i], bf[j][0], bf[j][1]);
        }
        // no trailing barrier: next iteration's top barrier protects reuse
    }
}

// ---------------- GEMM1: Q = X @ W^T, epilogue fp16 -----------------------
__global__ void __launch_bounds__(256, 2) gemm1_kernel() {
    extern __shared__ char sm[];
    uint32_t smb = s2u(sm);
    int tid = threadIdx.x, lane = tid & 31, wid = tid >> 5;
    int warp_m = wid & 3, warp_n = wid >> 2;
    int brow = blockIdx.y * 128, bn = blockIdx.x * 128;

    float acc[2][8][4];
    hmma_loop(g_A + (size_t)brow * KP, g_B + (size_t)bn * KP, smb, tid, acc);

    int row0 = brow + 32 * warp_m + (lane >> 2);
    int col0 = bn + 64 * warp_n + (lane & 3) * 2;
#pragma unroll
    for (int i = 0; i < 2; i++) {
#pragma unroll
        for (int j = 0; j < 8; j++) {
#pragma unroll
            for (int half = 0; half < 2; half++) {
                int r = row0 + 16 * i + 8 * half;
                int c = col0 + 8 * j;
                __half2 hh;
                hh.x = __float2half_rn(acc[i][j][2 * half]);
                hh.y = __float2half_rn(acc[i][j][2 * half + 1]);
                *reinterpret_cast<__half2*>(&g_Q[(size_t)r * KP + c]) = hh;
            }
        }
    }
}

// ---------------- GEMM2: out[n] = Q[n] @ R[n]^T, fp32 epilogue ------------
__global__ void __launch_bounds__(256, 2) gemm2_kernel(float* __restrict__ out) {
    extern __shared__ char sm[];
    uint32_t smb = s2u(sm);
    int tid = threadIdx.x, lane = tid & 31, wid = tid >> 5;
    int warp_m = wid & 3, warp_n = wid >> 2;
    int nb = blockIdx.z;
    int brow = blockIdx.y * 128, bn = blockIdx.x * 128;

    float acc[2][8][4];
    hmma_loop(g_Q + ((size_t)nb * LSEQ + brow) * KP,
              g_R + ((size_t)nb * LSEQ + bn) * KP, smb, tid, acc);

    int row0 = brow + 32 * warp_m + (lane >> 2);
    int col0 = bn + 64 * warp_n + (lane & 3) * 2;
    float* obase = out + (size_t)nb * LSEQ * LSEQ;
#pragma unroll
    for (int i = 0; i < 2; i++) {
#pragma unroll
        for (int j = 0; j < 8; j++) {
#pragma unroll
            for (int half = 0; half < 2; half++) {
                int r = row0 + 16 * i + 8 * half;
                int c = col0 + 8 * j;
                float2 v = make_float2(acc[i][j][2 * half], acc[i][j][2 * half + 1]);
                *reinterpret_cast<float2*>(&obase[(size_t)r * LSEQ + c]) = v;
            }
        }
    }
}

// ---------------- launcher ------------------------------------------------
extern "C" void kernel_launch(void* const* d_in, const int* in_sizes, int n_in,
                              void* d_out, int out_size) {
    const float* l1 = (const float*)d_in[0];
    const float* l2 = (const float*)d_in[1];
    const float* h1 = (const float*)d_in[3];
    const float* h2 = (const float*)d_in[4];
    const float* W  = (const float*)d_in[6];
    float* out = (float*)d_out;

    cudaFuncSetAttribute(gemm1_kernel, cudaFuncAttributeMaxDynamicSharedMemorySize, SMEM_SZ);
    cudaFuncSetAttribute(gemm2_kernel, cudaFuncAttributeMaxDynamicSharedMemorySize, SMEM_SZ);

    prep_XR<<<dim3(17, MROWS), 256>>>(l1, l2, h1, h2);
    prep_W<<<D65 * D65, 256>>>(W);
    gemm1_kernel<<<dim3(34, 64), 256, SMEM_SZ>>>();
    gemm2_kernel<<<dim3(8, 8, 8), 256, SMEM_SZ>>>(out);
}